// round 4
// baseline (speedup 1.0000x reference)
#include <cuda_runtime.h>
#include <cuda_bf16.h>
#include <math.h>

// Problem constants: B=32, N=128, D=256, H=8, DK=32
typedef unsigned int u32;

// ---------------- scratch (static device globals; no allocation) -------------
__device__ __align__(16) float g_fA[1024 * 256];
__device__ __align__(16) float g_fB[1024 * 256];
__device__ __align__(16) float g_conn[8 * 128 * 128];
__device__ __align__(16) float g_q[4096 * 256];     // [B,H,N,DK]
__device__ __align__(16) float g_k[4096 * 256];
__device__ __align__(16) float g_v[4096 * 256];

// bf16 split planes
__device__ __align__(16) __nv_bfloat16 g_whi[8 * 65536];  // mlp1,mlp2,q,k,v,out,fcA,fcB
__device__ __align__(16) __nv_bfloat16 g_wlo[8 * 65536];
__device__ __align__(16) __nv_bfloat16 g_h1hi[4096 * 256];
__device__ __align__(16) __nv_bfloat16 g_h1lo[4096 * 256];
__device__ __align__(16) __nv_bfloat16 g_xmhi[4096 * 256];
__device__ __align__(16) __nv_bfloat16 g_xmlo[4096 * 256];
__device__ __align__(16) __nv_bfloat16 g_aohi[4096 * 256];
__device__ __align__(16) __nv_bfloat16 g_aolo[4096 * 256];

__device__ __forceinline__ float gelu_tanh(float x) {
    float x3 = x * x * x;
    float t = tanhf(0.7978845608028654f * (x + 0.044715f * x3));
    return 0.5f * x * (1.0f + t);
}

__device__ __forceinline__ void split_bf16(float v, __nv_bfloat16& h, __nv_bfloat16& l) {
    h = __float2bfloat16_rn(v);
    l = __float2bfloat16_rn(v - __bfloat162float(h));
}

__device__ __forceinline__ void cvt4(float4 v, uint2& hi, uint2& lo) {
    __nv_bfloat16 h0, l0, h1, l1, h2, l2, h3, l3;
    split_bf16(v.x, h0, l0); split_bf16(v.y, h1, l1);
    split_bf16(v.z, h2, l2); split_bf16(v.w, h3, l3);
    __nv_bfloat162 a, b, c, d;
    a.x = h0; a.y = h1; b.x = h2; b.y = h3;
    c.x = l0; c.y = l1; d.x = l2; d.y = l3;
    hi.x = *(u32*)&a; hi.y = *(u32*)&b;
    lo.x = *(u32*)&c; lo.y = *(u32*)&d;
}

#define LDSM4(r, addr)                                                        \
    asm volatile("ldmatrix.sync.aligned.m8n8.x4.shared.b16 {%0,%1,%2,%3}, [%4];" \
                 : "=r"(r[0]), "=r"(r[1]), "=r"(r[2]), "=r"(r[3]) : "r"(addr))

#define LDSM4T(r, addr)                                                       \
    asm volatile("ldmatrix.sync.aligned.m8n8.x4.trans.shared.b16 {%0,%1,%2,%3}, [%4];" \
                 : "=r"(r[0]), "=r"(r[1]), "=r"(r[2]), "=r"(r[3]) : "r"(addr))

#define MMA16816(d, a, b)                                                     \
    asm volatile("mma.sync.aligned.m16n8k16.row.col.f32.bf16.bf16.f32 "       \
                 "{%0,%1,%2,%3}, {%4,%5,%6,%7}, {%8,%9}, {%0,%1,%2,%3};"      \
                 : "+f"(d[0]), "+f"(d[1]), "+f"(d[2]), "+f"(d[3])             \
                 : "r"(a[0]), "r"(a[1]), "r"(a[2]), "r"(a[3]),                \
                   "r"(b[0]), "r"(b[1]))

// ---------------- convert weights to bf16 hi/lo planes -----------------------
struct WPtrs { const float* p[8]; };

__global__ void k_cvtW(WPtrs P) {
    int wy = blockIdx.y;
    const float* src = P.p[wy];
    int t = threadIdx.x;
    int base = blockIdx.x * 2048;
    #pragma unroll
    for (int i = 0; i < 8; i++) {
        int idx = base + i * 256 + t;
        __nv_bfloat16 h, l;
        split_bf16(src[idx], h, l);
        g_whi[wy * 65536 + idx] = h;
        g_wlo[wy * 65536 + idx] = l;
    }
}

// ---------------- tensor-core GEMM with job dispatch -------------------------
// BM=64, BN=64, BK=32, 8 warps (4x2), warp tile 16x32, double-buffered.
// Split-bf16: acc += AhWh + AhWl + AlWh.
struct Job {
    const float* Af;                 // fp32 A (aMode 0/1)
    const __nv_bfloat16 *Ahi, *Alo;  // bf16 plane A (aMode 2)
    const float* bias;
    float* Cf;
    __nv_bfloat16 *Chi, *Clo;
    int wIdx;       // weight plane index into g_whi/g_wlo
    int mBlocks;    // blocks along M actually used
    int aMode;      // 0 fp32 row-major, 1 fp32 memory_w gather, 2 bf16 planes
    int act;        // gelu on output
    int storeMode;  // 0 fp32 C, 1 bf16 planes, 2 fp32 QKV permute
};

__global__ void __launch_bounds__(256)
k_mma(Job j0, Job j1, Job j2)
{
    const Job& J = (blockIdx.z == 0) ? j0 : (blockIdx.z == 1) ? j1 : j2;
    if (blockIdx.x >= (unsigned)J.mBlocks) return;

    __shared__ __nv_bfloat16 sAhi[2][64 * 40];
    __shared__ __nv_bfloat16 sAlo[2][64 * 40];
    __shared__ __nv_bfloat16 sWhi[2][32 * 72];
    __shared__ __nv_bfloat16 sWlo[2][32 * 72];

    const __nv_bfloat16* Wh = g_whi + (size_t)J.wIdx * 65536;
    const __nv_bfloat16* Wl = g_wlo + (size_t)J.wIdx * 65536;

    int t = threadIdx.x;
    int warp = t >> 5, lane = t & 31;
    int wm = warp >> 1, wn = warp & 1;
    int rowBase = blockIdx.x * 64;
    int colBase = blockIdx.y * 64;
    int g = lane >> 3, r = lane & 7;

    u32 sAhiB = (u32)__cvta_generic_to_shared(sAhi);
    u32 sAloB = (u32)__cvta_generic_to_shared(sAlo);
    u32 sWhiB = (u32)__cvta_generic_to_shared(sWhi);
    u32 sWloB = (u32)__cvta_generic_to_shared(sWlo);
    const u32 ABUF = 64 * 40 * 2;   // bytes per A buffer
    const u32 WBUF = 32 * 72 * 2;

    // A staging indices
    int arow = t >> 3, aseg = t & 7;         // fp32: 2 chunks (this + +256)
    int arow2 = (t + 256) >> 3, aseg2 = (t + 256) & 7;
    int prow = t >> 2, pseg = t & 3;         // bf16 planes: 1 chunk of 8
    int wrow = t >> 3, wseg = t & 7;         // W: 1 chunk of 8 per plane

    // prefetch registers
    float4 fa0, fa1;
    uint4 pah, pal, pwh, pwl;

    auto loadTile = [&](int kt) {
        if (J.aMode == 2) {
            int gidx = (rowBase + prow) * 256 + kt + pseg * 8;
            pah = *(const uint4*)&J.Ahi[gidx];
            pal = *(const uint4*)&J.Alo[gidx];
        } else if (J.aMode == 0) {
            fa0 = *(const float4*)&J.Af[(rowBase + arow) * 256 + kt + aseg * 4];
            fa1 = *(const float4*)&J.Af[(rowBase + arow2) * 256 + kt + aseg2 * 4];
        } else {
            int rr = rowBase + arow;  int h = rr >> 7,  n = rr & 127;
            int rr2 = rowBase + arow2; int h2 = rr2 >> 7, n2 = rr2 & 127;
            fa0 = *(const float4*)&J.Af[n * 2048 + h * 256 + kt + aseg * 4];
            fa1 = *(const float4*)&J.Af[n2 * 2048 + h2 * 256 + kt + aseg2 * 4];
        }
        int gw = (kt + wrow) * 256 + colBase + wseg * 8;
        pwh = *(const uint4*)&Wh[gw];
        pwl = *(const uint4*)&Wl[gw];
    };

    auto storeTile = [&](int bb) {
        if (J.aMode == 2) {
            int soff = prow * 40 + pseg * 8;
            *(uint4*)&sAhi[bb][soff] = pah;
            *(uint4*)&sAlo[bb][soff] = pal;
        } else {
            uint2 hi, lo;
            cvt4(fa0, hi, lo);
            *(uint2*)&sAhi[bb][arow * 40 + aseg * 4] = hi;
            *(uint2*)&sAlo[bb][arow * 40 + aseg * 4] = lo;
            cvt4(fa1, hi, lo);
            *(uint2*)&sAhi[bb][arow2 * 40 + aseg2 * 4] = hi;
            *(uint2*)&sAlo[bb][arow2 * 40 + aseg2 * 4] = lo;
        }
        int soff = wrow * 72 + wseg * 8;
        *(uint4*)&sWhi[bb][soff] = pwh;
        *(uint4*)&sWlo[bb][soff] = pwl;
    };

    float acc[4][4];
    #pragma unroll
    for (int nt = 0; nt < 4; nt++)
        #pragma unroll
        for (int i = 0; i < 4; i++) acc[nt][i] = 0.0f;

    loadTile(0);
    storeTile(0);
    __syncthreads();

    #pragma unroll
    for (int it = 0; it < 8; it++) {
        int bb = it & 1;
        if (it < 7) loadTile((it + 1) * 32);

        #pragma unroll
        for (int ks = 0; ks < 32; ks += 16) {
            u32 ah[4], al[4], bh[2][4], bl[2][4];
            {
                int rowA = wm * 16 + r + ((g & 1) << 3);
                int kcol = ks + ((g >> 1) << 3);
                u32 off = bb * ABUF + (u32)(rowA * 40 + kcol) * 2;
                LDSM4(ah, sAhiB + off);
                LDSM4(al, sAloB + off);
            }
            #pragma unroll
            for (int np = 0; np < 2; np++) {
                int krow = ks + r + ((g & 1) << 3);
                int ncol = wn * 32 + np * 16 + ((g >> 1) << 3);
                u32 off = bb * WBUF + (u32)(krow * 72 + ncol) * 2;
                LDSM4T(bh[np], sWhiB + off);
                LDSM4T(bl[np], sWloB + off);
            }
            #pragma unroll
            for (int nt = 0; nt < 4; nt++) {
                const u32* Bh = &bh[nt >> 1][(nt & 1) * 2];
                const u32* Bl = &bl[nt >> 1][(nt & 1) * 2];
                MMA16816(acc[nt], ah, Bh);
                MMA16816(acc[nt], ah, Bl);
                MMA16816(acc[nt], al, Bh);
            }
        }
        __syncthreads();
        if (it < 7) {
            storeTile(1 - bb);
            __syncthreads();
        }
    }

    // ---------------- epilogue ----------------
    #pragma unroll
    for (int nt = 0; nt < 4; nt++) {
        int row0 = rowBase + wm * 16 + (lane >> 2);
        int col0 = colBase + wn * 32 + nt * 8 + (lane & 3) * 2;
        float bv0 = J.bias ? J.bias[col0] : 0.0f;
        float bv1 = J.bias ? J.bias[col0 + 1] : 0.0f;
        #pragma unroll
        for (int half = 0; half < 2; half++) {
            int row = row0 + half * 8;
            float v0 = acc[nt][half * 2 + 0] + bv0;
            float v1 = acc[nt][half * 2 + 1] + bv1;
            if (J.act) { v0 = gelu_tanh(v0); v1 = gelu_tanh(v1); }
            if (J.storeMode == 0) {
                *(float2*)&J.Cf[row * 256 + col0] = make_float2(v0, v1);
            } else if (J.storeMode == 1) {
                __nv_bfloat16 h0, l0, h1, l1;
                split_bf16(v0, h0, l0);
                split_bf16(v1, h1, l1);
                __nv_bfloat162 H; H.x = h0; H.y = h1;
                __nv_bfloat162 L; L.x = l0; L.y = l1;
                *(__nv_bfloat162*)&J.Chi[row * 256 + col0] = H;
                *(__nv_bfloat162*)&J.Clo[row * 256 + col0] = L;
            } else {
                int b = row >> 7, n = row & 127;
                int h = col0 >> 5, dk = col0 & 31;
                *(float2*)&J.Cf[(((b * 8 + h) * 128 + n) * 32) + dk] = make_float2(v0, v1);
            }
        }
    }
}

// ---------------- connection mask, tiled, no reductions ----------------------
__global__ void k_conn(const float* __restrict__ fA, const float* __restrict__ fB,
                       const float* __restrict__ ob, const float* __restrict__ cw,
                       const float* __restrict__ cb, const float* __restrict__ gu,
                       float* __restrict__ conn)
{
    __shared__ float Aj[32][33];
    __shared__ float Bi[16][33];
    __shared__ float Cs0[256], Cs1[256];

    int h = blockIdx.x;
    int ibase = blockIdx.y * 16;
    int jbase = blockIdx.z * 32;
    int t = threadIdx.x;          // 128
    int tx = t & 15, ty = t >> 4;

    for (int d = t; d < 256; d += 128) {
        Cs0[d] = cw[2 * d];
        Cs1[d] = cw[2 * d + 1];
    }

    float l0[2][2] = {{0.f, 0.f}, {0.f, 0.f}};
    float l1[2][2] = {{0.f, 0.f}, {0.f, 0.f}};

    for (int d0 = 0; d0 < 256; d0 += 32) {
        __syncthreads();
        #pragma unroll
        for (int u = 0; u < 2; u++) {
            int s = t * 2 + u;
            int j = s >> 3, c = (s & 7) * 4;
            float4 v = *(const float4*)&fA[(h * 128 + jbase + j) * 256 + d0 + c];
            Aj[j][c] = v.x; Aj[j][c + 1] = v.y; Aj[j][c + 2] = v.z; Aj[j][c + 3] = v.w;
        }
        {
            int i = t >> 3, c = (t & 7) * 4;
            float4 v = *(const float4*)&fB[(h * 128 + ibase + i) * 256 + d0 + c];
            float4 o = *(const float4*)&ob[d0 + c];
            Bi[i][c] = v.x + o.x; Bi[i][c + 1] = v.y + o.y;
            Bi[i][c + 2] = v.z + o.z; Bi[i][c + 3] = v.w + o.w;
        }
        __syncthreads();

        #pragma unroll
        for (int dd = 0; dd < 32; dd++) {
            float a0 = Aj[tx * 2][dd], a1 = Aj[tx * 2 + 1][dd];
            float b0 = Bi[ty * 2][dd], b1 = Bi[ty * 2 + 1][dd];
            float c0v = Cs0[d0 + dd], c1v = Cs1[d0 + dd];
            float r00 = fmaxf(a0 + b0, 0.f), r10 = fmaxf(a1 + b0, 0.f);
            float r01 = fmaxf(a0 + b1, 0.f), r11 = fmaxf(a1 + b1, 0.f);
            l0[0][0] = fmaf(r00, c0v, l0[0][0]); l1[0][0] = fmaf(r00, c1v, l1[0][0]);
            l0[0][1] = fmaf(r10, c0v, l0[0][1]); l1[0][1] = fmaf(r10, c1v, l1[0][1]);
            l0[1][0] = fmaf(r01, c0v, l0[1][0]); l1[1][0] = fmaf(r01, c1v, l1[1][0]);
            l0[1][1] = fmaf(r11, c0v, l0[1][1]); l1[1][1] = fmaf(r11, c1v, l1[1][1]);
        }
    }

    float cb0 = cb[0], cb1 = cb[1];
    #pragma unroll
    for (int ii = 0; ii < 2; ii++) {
        int i = ibase + ty * 2 + ii;
        #pragma unroll
        for (int jj = 0; jj < 2; jj++) {
            int j = jbase + tx * 2 + jj;
            int idx = (h * 128 + i) * 128 + j;
            float2 u2 = *(const float2*)&gu[idx * 2];
            float g0 = -logf(-logf(u2.x + 1e-10f) + 1e-10f);
            float g1 = -logf(-logf(u2.y + 1e-10f) + 1e-10f);
            conn[idx] = ((l1[ii][jj] + cb1 + g1) > (l0[ii][jj] + cb0 + g0)) ? 1.0f : 0.0f;
        }
    }
}

// ---------------- masked attention, one block per (b,h), 128 threads ---------
#define SC_FLOATS (128 * 129)
#define KV_FLOATS (128 * 32)
#define SMEM_ATTN ((SC_FLOATS + KV_FLOATS) * 4 + 128 * 4 * 4)

__global__ void k_attn(const float* __restrict__ q, const float* __restrict__ k,
                       const float* __restrict__ v, const float* __restrict__ conn,
                       __nv_bfloat16* __restrict__ aohi, __nv_bfloat16* __restrict__ aolo)
{
    extern __shared__ float sm[];
    float* sc = sm;                       // 128*129
    float* kv = sm + SC_FLOATS;           // 128*32
    unsigned* cmask = (unsigned*)(kv + KV_FLOATS);

    int bid = blockIdx.x;
    int b = bid >> 3, h = bid & 7;
    int t = threadIdx.x, w = t >> 5, lane = t & 31;

    const float* cr = conn + h * 16384;
    for (int i0 = 0; i0 < 128; i0++) {
        float c = cr[i0 * 128 + t];
        unsigned bal = __ballot_sync(0xffffffffu, c > 0.5f);
        if (lane == 0) cmask[i0 * 4 + w] = bal;
    }

    for (int idx = t; idx < KV_FLOATS; idx += 128) kv[idx] = k[bid * 4096 + idx];
    __syncthreads();

    float4 qr[8];
    const float4* qp = (const float4*)(q + (bid * 128 + t) * 32);
    #pragma unroll
    for (int d = 0; d < 8; d++) qr[d] = qp[d];

    unsigned marr[4];
    #pragma unroll
    for (int u = 0; u < 4; u++) marr[u] = cmask[t * 4 + u];

    const float scale = 0.17677669529663687f;  // 1/sqrt(32)
    const float4* kv4 = (const float4*)kv;
    float mx = -INFINITY;

    for (int wdx = 0; wdx < 4; wdx++) {
        unsigned word = marr[wdx];
        for (int jj = 0; jj < 32; jj++) {
            int j = (wdx << 5) | jj;
            float s;
            if ((word >> jj) & 1u) {
                float a0 = 0.f, a1 = 0.f, a2 = 0.f, a3 = 0.f;
                #pragma unroll
                for (int d = 0; d < 8; d++) {
                    float4 kk4 = kv4[j * 8 + d];
                    a0 = fmaf(qr[d].x, kk4.x, a0);
                    a1 = fmaf(qr[d].y, kk4.y, a1);
                    a2 = fmaf(qr[d].z, kk4.z, a2);
                    a3 = fmaf(qr[d].w, kk4.w, a3);
                }
                s = ((a0 + a1) + (a2 + a3)) * scale;
                mx = fmaxf(mx, s);
            } else {
                s = -INFINITY;
            }
            sc[t * 129 + j] = s;
        }
    }
    __syncthreads();

    for (int idx = t; idx < KV_FLOATS; idx += 128) kv[idx] = v[bid * 4096 + idx];

    float sum = 0.0f;
    for (int j = 0; j < 128; j++) {
        float e = expf(sc[t * 129 + j] - mx);
        sum += e;
        sc[t * 129 + j] = e;
    }
    float inv = 1.0f / sum;
    __syncthreads();

    float acc[32];
    #pragma unroll
    for (int d = 0; d < 32; d++) acc[d] = 0.0f;

    for (int j = 0; j < 128; j++) {
        float p = sc[t * 129 + j];
        #pragma unroll
        for (int dd = 0; dd < 8; dd++) {
            float4 vv = kv4[j * 8 + dd];
            acc[dd * 4 + 0] = fmaf(p, vv.x, acc[dd * 4 + 0]);
            acc[dd * 4 + 1] = fmaf(p, vv.y, acc[dd * 4 + 1]);
            acc[dd * 4 + 2] = fmaf(p, vv.z, acc[dd * 4 + 2]);
            acc[dd * 4 + 3] = fmaf(p, vv.w, acc[dd * 4 + 3]);
        }
    }

    int obase = (b * 128 + t) * 256 + h * 32;
    #pragma unroll
    for (int d = 0; d < 32; d += 2) {
        float v0 = acc[d] * inv, v1 = acc[d + 1] * inv;
        __nv_bfloat16 h0, l0, h1, l1;
        split_bf16(v0, h0, l0);
        split_bf16(v1, h1, l1);
        __nv_bfloat162 H; H.x = h0; H.y = h1;
        __nv_bfloat162 L; L.x = l0; L.y = l1;
        *(__nv_bfloat162*)&aohi[obase + d] = H;
        *(__nv_bfloat162*)&aolo[obase + d] = L;
    }
}

// ---------------- launch ------------------------------------------------------
extern "C" void kernel_launch(void* const* d_in, const int* in_sizes, int n_in,
                              void* d_out, int out_size)
{
    const float* x        = (const float*)d_in[0];
    const float* gumbel_u = (const float*)d_in[1];
    const float* memory_w = (const float*)d_in[2];
    const float* fc_out_w = (const float*)d_in[3];
    const float* fc_out_b = (const float*)d_in[4];
    const float* fc_cat_w = (const float*)d_in[5];
    const float* fc_cat_b = (const float*)d_in[6];
    const float* wq       = (const float*)d_in[7];
    const float* bq       = (const float*)d_in[8];
    const float* wk       = (const float*)d_in[9];
    const float* bk       = (const float*)d_in[10];
    const float* wv       = (const float*)d_in[11];
    const float* bv       = (const float*)d_in[12];
    const float* out_w    = (const float*)d_in[13];
    const float* out_b    = (const float*)d_in[14];
    const float* mlp_w1   = (const float*)d_in[15];
    const float* mlp_b1   = (const float*)d_in[16];
    const float* mlp_w2   = (const float*)d_in[17];
    const float* mlp_b2   = (const float*)d_in[18];

    float *fA, *fB, *conn, *q, *k, *v;
    cudaGetSymbolAddress((void**)&fA, g_fA);
    cudaGetSymbolAddress((void**)&fB, g_fB);
    cudaGetSymbolAddress((void**)&conn, g_conn);
    cudaGetSymbolAddress((void**)&q, g_q);
    cudaGetSymbolAddress((void**)&k, g_k);
    cudaGetSymbolAddress((void**)&v, g_v);

    __nv_bfloat16 *h1hi, *h1lo, *xmhi, *xmlo, *aohi, *aolo;
    cudaGetSymbolAddress((void**)&h1hi, g_h1hi);
    cudaGetSymbolAddress((void**)&h1lo, g_h1lo);
    cudaGetSymbolAddress((void**)&xmhi, g_xmhi);
    cudaGetSymbolAddress((void**)&xmlo, g_xmlo);
    cudaGetSymbolAddress((void**)&aohi, g_aohi);
    cudaGetSymbolAddress((void**)&aolo, g_aolo);

    cudaFuncSetAttribute(k_attn, cudaFuncAttributeMaxDynamicSharedMemorySize, SMEM_ATTN);

    // weight planes: [0]=mlp_w1 [1]=mlp_w2 [2]=wq [3]=wk [4]=wv [5]=out_w [6]=fcA [7]=fcB
    WPtrs P;
    P.p[0] = mlp_w1; P.p[1] = mlp_w2; P.p[2] = wq; P.p[3] = wk;
    P.p[4] = wv; P.p[5] = out_w; P.p[6] = fc_out_w; P.p[7] = fc_out_w + 65536;
    k_cvtW<<<dim3(32, 8), 256>>>(P);

    Job JZ = {};  // zero job

    // mega launch 1: z0 = fA, z1 = fB (memory_w gather), z2 = mlp1 (x, gelu)
    {
        Job ja = JZ, jb = JZ, jm = JZ;
        ja.Af = memory_w; ja.Cf = fA; ja.wIdx = 6; ja.mBlocks = 16; ja.aMode = 1;
        jb.Af = memory_w; jb.Cf = fB; jb.wIdx = 7; jb.mBlocks = 16; jb.aMode = 1;
        jm.Af = x; jm.bias = mlp_b1; jm.Chi = h1hi; jm.Clo = h1lo;
        jm.wIdx = 0; jm.mBlocks = 64; jm.aMode = 0; jm.act = 1; jm.storeMode = 1;
        k_mma<<<dim3(64, 4, 3), 256>>>(ja, jb, jm);
    }

    // conn (depends on fA/fB only)
    k_conn<<<dim3(8, 8, 4), 128>>>(fA, fB, fc_out_b, fc_cat_w, fc_cat_b, gumbel_u, conn);

    // mlp2
    {
        Job j = JZ;
        j.Ahi = h1hi; j.Alo = h1lo; j.bias = mlp_b2; j.Chi = xmhi; j.Clo = xmlo;
        j.wIdx = 1; j.mBlocks = 64; j.aMode = 2; j.storeMode = 1;
        k_mma<<<dim3(64, 4, 1), 256>>>(j, JZ, JZ);
    }

    // QKV fused
    {
        Job jq = JZ, jk = JZ, jv = JZ;
        jq.Ahi = xmhi; jq.Alo = xmlo; jq.bias = bq; jq.Cf = q;
        jq.wIdx = 2; jq.mBlocks = 64; jq.aMode = 2; jq.storeMode = 2;
        jk = jq; jk.bias = bk; jk.Cf = k; jk.wIdx = 3;
        jv = jq; jv.bias = bv; jv.Cf = v; jv.wIdx = 4;
        k_mma<<<dim3(64, 4, 3), 256>>>(jq, jk, jv);
    }

    // masked attention -> ao planes
    k_attn<<<256, 128, SMEM_ATTN>>>(q, k, v, conn, aohi, aolo);

    // output projection -> d_out (fp32)
    {
        Job j = JZ;
        j.Ahi = aohi; j.Alo = aolo; j.bias = out_b; j.Cf = (float*)d_out;
        j.wIdx = 5; j.mBlocks = 64; j.aMode = 2; j.storeMode = 0;
        k_mma<<<dim3(64, 4, 1), 256>>>(j, JZ, JZ);
    }
}